// round 4
// baseline (speedup 1.0000x reference)
#include <cuda_runtime.h>

// Shape (N,C,T,V,M) = (256,3,600,25,2), f32
#define NB       256
#define TT       600
#define VV       25
#define ROWS     1800              // C*T rows of 50 floats per sample
#define F2_N     (ROWS * VV)       // 45000 float2 per sample
#define CHUNKS   4
#define CROWS    (ROWS / CHUNKS)   // 450 rows per chunk
#define THREADS  250               // multiple of 25 -> fixed joint per thread
#define ROWS_IT  (THREADS / VV)    // 10 rows per iteration
#define ITERS    (CROWS / ROWS_IT) // 45 iterations
#define NTOT     23040000.0f

// Deterministic chunk partials (plain stores, no FP atomics)
__device__ float        gAbs[NB][CHUNKS][VV];
__device__ float        gSq [NB][CHUNKS][VV];
__device__ float        g_partial[NB];
__device__ unsigned int g_cnt[NB];   // per-sample chunk counters (self-resetting)
__device__ unsigned int g_count;     // global sample counter (self-resetting)

__global__ __launch_bounds__(THREADS, 4)
void loss_fused(const float2* __restrict__ x, const float2* __restrict__ y,
                float* __restrict__ out)
{
    const int b     = blockIdx.x;      // 0..1023
    const int n     = b >> 2;
    const int chunk = b & 3;
    const int tid   = threadIdx.x;
    const int v     = tid % VV;
    const int r0    = tid / VV;

    const size_t base = (size_t)n * F2_N + (size_t)chunk * (CROWS * VV);
    const float2* __restrict__ xb = x + base;
    const float2* __restrict__ yb = y + base;

    __shared__ float sAbs[VV];
    __shared__ float sSq[VV];
    __shared__ bool  sLastChunk;
    __shared__ bool  sFinal;
    if (tid < VV) { sAbs[tid] = 0.0f; sSq[tid] = 0.0f; }
    if (tid == 0) { sLastChunk = false; sFinal = false; }
    __syncthreads();

    float accA = 0.0f;   // sum |x[t+1]-x[t]|
    float accS = 0.0f;   // sum (x-y)^2

    #pragma unroll 5
    for (int j = 0; j < ITERS; ++j) {
        const int idx  = tid + j * THREADS;            // float2 idx within chunk
        const int row  = chunk * CROWS + r0 + j * ROWS_IT;  // global row
        const int t    = row % TT;

        const float2 a  = __ldg(&xb[idx]);
        const float2 yv = __ldcs(&yb[idx]);            // read-once: evict-first
        const float dx = a.x - yv.x;
        const float dy = a.y - yv.y;
        accS = fmaf(dx, dx, accS);
        accS = fmaf(dy, dy, accS);

        if (t != TT - 1) {                             // diff stays within channel
            const float2 bnext = __ldg(&xb[idx + VV]); // may cross chunk bound (ok)
            accA += fabsf(bnext.x - a.x) + fabsf(bnext.y - a.y);
        }
    }

    atomicAdd(&sAbs[v], accA);   // 10 threads per joint slot
    atomicAdd(&sSq[v],  accS);
    __syncthreads();

    // Publish chunk partials; 4th-arriving chunk block finalizes the sample
    if (tid < VV) {
        gAbs[n][chunk][tid] = sAbs[tid];
        gSq [n][chunk][tid] = sSq[tid];
    }
    __syncthreads();
    if (tid == 0) {
        __threadfence();
        unsigned int prev = atomicAdd(&g_cnt[n], 1u);
        sLastChunk = (prev == CHUNKS - 1);
    }
    __syncthreads();

    if (sLastChunk) {
        if (tid < 32) {
            __threadfence();
            float av = 0.0f, sv = 0.0f;
            if (tid < VV) {
                #pragma unroll
                for (int c = 0; c < CHUNKS; ++c) {       // fixed order: deterministic
                    av += __ldcg(&gAbs[n][c][tid]);
                    sv += __ldcg(&gSq [n][c][tid]);
                }
            }
            float tot = av;
            #pragma unroll
            for (int o = 16; o > 0; o >>= 1)
                tot += __shfl_xor_sync(0xffffffffu, tot, o);

            float contrib = av * sv;
            #pragma unroll
            for (int o = 16; o > 0; o >>= 1)
                contrib += __shfl_xor_sync(0xffffffffu, contrib, o);

            if (tid == 0) {
                g_partial[n] = (float)VV * contrib / tot;
                g_cnt[n]     = 0u;                       // rearm for next replay
                __threadfence();
                unsigned int p2 = atomicAdd(&g_count, 1u);
                sFinal = (p2 == NB - 1);
            }
        }
        __syncthreads();

        // Last sample-finalizer on the whole chip: reduce 256 partials
        if (sFinal && tid < 32) {
            __threadfence();
            float val = 0.0f;
            #pragma unroll
            for (int k = 0; k < NB / 32; ++k)
                val += __ldcg(&g_partial[tid + k * 32]);
            #pragma unroll
            for (int o = 16; o > 0; o >>= 1)
                val += __shfl_xor_sync(0xffffffffu, val, o);
            if (tid == 0) {
                out[0]  = val / NTOT;
                g_count = 0u;                            // rearm
                __threadfence();
            }
        }
    }
}

extern "C" void kernel_launch(void* const* d_in, const int* in_sizes, int n_in,
                              void* d_out, int out_size)
{
    (void)in_sizes; (void)n_in; (void)out_size;
    loss_fused<<<NB * CHUNKS, THREADS>>>((const float2*)d_in[0],
                                         (const float2*)d_in[1],
                                         (float*)d_out);
}